// round 4
// baseline (speedup 1.0000x reference)
#include <cuda_runtime.h>
#include <cstdint>

#define THREADS   512
#define KVAL      10
#define NCOLS     100000
#define NVEC      (NCOLS / 4)     // 25000 float4 per row
#define FULL_T    48              // 48 full strided iterations (12 x unroll4), +1 tail

// Monotonic bijection fp32 -> uint32 preserving order (no NaNs in data).
__device__ __forceinline__ unsigned flip_f32(float f) {
    unsigned u = __float_as_uint(f);
    return (u & 0x80000000u) ? ~u : (u | 0x80000000u);
}
__device__ __forceinline__ float unflip_f32(unsigned u) {
    unsigned b = (u & 0x80000000u) ? (u ^ 0x80000000u) : ~u;
    return __uint_as_float(b);
}

__global__ __launch_bounds__(THREADS, 2)
void topk_kernel(const float* __restrict__ scores, float* __restrict__ out, int B) {
    __shared__ unsigned long long s_buf[THREADS * KVAL];   // 40 KB
    __shared__ unsigned long long s_wbest[THREADS / 32];
    __shared__ int                s_wpos[THREADS / 32];
    __shared__ unsigned long long s_top[KVAL];

    const int tid = threadIdx.x;
    const int row = blockIdx.x;
    const float4* __restrict__ r4 =
        (const float4*)(scores + (size_t)row * NCOLS);

    // ---- per-thread top-10 in registers, key = (flip(v) << 32) | ~idx
    unsigned long long keys[KVAL];
    #pragma unroll
    for (int j = 0; j < KVAL; j++) keys[j] = 0ull;
    unsigned long long kmin  = 0ull;
    unsigned           thr_u = 0u;          // flipped-domain threshold = kmin >> 32

    auto consider4 = [&](float4 v, int gi) {
        float m = fmaxf(fmaxf(v.x, v.y), fmaxf(v.z, v.w));
        if (flip_f32(m) >= thr_u) {         // rare after first ~10 elements
            float vv[4] = {v.x, v.y, v.z, v.w};
            #pragma unroll
            for (int e = 0; e < 4; e++) {
                unsigned long long key =
                    ((unsigned long long)flip_f32(vv[e]) << 32) |
                    (unsigned)(~(gi + e));
                if (key > kmin) {
                    bool done = false;
                    #pragma unroll
                    for (int j = 0; j < KVAL; j++)
                        if (!done && keys[j] == kmin) { keys[j] = key; done = true; }
                    kmin = keys[0];
                    #pragma unroll
                    for (int j = 1; j < KVAL; j++) kmin = min(kmin, keys[j]);
                    thr_u = (unsigned)(kmin >> 32);
                }
            }
        }
    };

    // ---- barrier-free streaming loop, 4 independent LDG.128 in flight
    #pragma unroll 1
    for (int t = 0; t < FULL_T; t += 4) {
        const int i0 = tid + (t + 0) * THREADS;
        const int i1 = tid + (t + 1) * THREADS;
        const int i2 = tid + (t + 2) * THREADS;
        const int i3 = tid + (t + 3) * THREADS;
        float4 a = __ldcs(&r4[i0]);
        float4 b = __ldcs(&r4[i1]);
        float4 c = __ldcs(&r4[i2]);
        float4 d = __ldcs(&r4[i3]);
        consider4(a, i0 * 4);
        consider4(b, i1 * 4);
        consider4(c, i2 * 4);
        consider4(d, i3 * 4);
    }
    {   // tail iteration (only threads with tid < 25000 - 48*512 = 424)
        const int i = tid + FULL_T * THREADS;
        if (i < NVEC) consider4(__ldcs(&r4[i]), i * 4);
    }

    // ---- dump per-thread top-10 to shared (every thread saw >=192 elems, all keys real)
    #pragma unroll
    for (int j = 0; j < KVAL; j++) s_buf[tid * KVAL + j] = keys[j];
    __syncthreads();

    // ---- block selection: extract top-10 of the 5120 candidates
    const int C = THREADS * KVAL;
    #pragma unroll 1
    for (int sel = 0; sel < KVAL; sel++) {
        unsigned long long best = 0ull;
        int bpos = -1;
        #pragma unroll
        for (int j = tid; j < C; j += THREADS) {
            unsigned long long k = s_buf[j];
            if (k > best) { best = k; bpos = j; }
        }
        #pragma unroll
        for (int o = 16; o > 0; o >>= 1) {
            unsigned long long ob = __shfl_down_sync(0xffffffffu, best, o);
            int op               = __shfl_down_sync(0xffffffffu, bpos, o);
            if (ob > best) { best = ob; bpos = op; }
        }
        if ((tid & 31) == 0) {
            s_wbest[tid >> 5] = best;
            s_wpos [tid >> 5] = bpos;
        }
        __syncthreads();
        if (tid == 0) {
            unsigned long long bb = 0ull; int bp = -1;
            #pragma unroll
            for (int w = 0; w < THREADS / 32; w++)
                if (s_wbest[w] > bb) { bb = s_wbest[w]; bp = s_wpos[w]; }
            s_top[sel] = bb;
            if (bp >= 0) s_buf[bp] = 0ull;     // remove winner (keys unique by idx)
        }
        __syncthreads();
    }

    // ---- write out: [B*K indices (as float)] then [B*K scores]
    if (tid < KVAL) {
        unsigned long long key = s_top[tid];
        float val = unflip_f32((unsigned)(key >> 32));
        int   idx = (int)(~(unsigned)key);
        out[(size_t)row * KVAL + tid]                    = (float)idx;
        out[(size_t)B * KVAL + (size_t)row * KVAL + tid] = val;
    }
}

extern "C" void kernel_launch(void* const* d_in, const int* in_sizes, int n_in,
                              void* d_out, int out_size) {
    const float* scores = (const float*)d_in[0];
    const int B = in_sizes[0] / NCOLS;      // 2048
    (void)n_in; (void)out_size;
    topk_kernel<<<B, THREADS>>>(scores, (float*)d_out, B);
}

// round 5
// speedup vs baseline: 8.3281x; 8.3281x over previous
#include <cuda_runtime.h>
#include <cstdint>

#define THREADS   512
#define KVAL      10
#define NCOLS     100000
#define NVEC      (NCOLS / 4)       // 25000 float4 per row
#define CAP       4096              // shared candidate buffer (uint64 keys)
#define UNR       8                 // loads in flight per thread in stream phase

// Monotonic bijection fp32 -> uint32 preserving order (no NaNs in data).
__device__ __forceinline__ unsigned flip_f32(float f) {
    unsigned u = __float_as_uint(f);
    return (u & 0x80000000u) ? ~u : (u | 0x80000000u);
}
__device__ __forceinline__ float unflip_f32(unsigned u) {
    unsigned b = (u & 0x80000000u) ? (u ^ 0x80000000u) : ~u;
    return __uint_as_float(b);
}
// key = (flip(v) << 32) | ~idx : uint64 max == larger value, then smaller index
__device__ __forceinline__ unsigned long long mk_key(float v, int idx) {
    return ((unsigned long long)flip_f32(v) << 32) | (unsigned)(~idx);
}

__global__ __launch_bounds__(THREADS, 2)
void topk_kernel(const float* __restrict__ scores, float* __restrict__ out, int B) {
    __shared__ unsigned long long s_buf[CAP];            // 32 KB
    __shared__ unsigned long long s_wbest[THREADS / 32];
    __shared__ int                s_wpos[THREADS / 32];
    __shared__ unsigned long long s_top[KVAL];
    __shared__ int                s_count;
    __shared__ int                s_over;
    __shared__ unsigned           s_thr;                 // flipped-domain threshold

    const int tid = threadIdx.x;
    const int row = blockIdx.x;
    const float4* __restrict__ r4 = (const float4*)(scores + (size_t)row * NCOLS);

    // ---- selection-with-removal: top-10 of s_buf[0..min(count,CAP)) -> s_top,
    //      compact into s_buf[0..9], set count=10 and thr = 10th value.
    auto prune = [&]() {
        const int c = min(s_count, CAP);
        #pragma unroll 1
        for (int sel = 0; sel < KVAL; sel++) {
            unsigned long long best = 0ull;
            int bpos = -1;
            for (int j = tid; j < c; j += THREADS) {
                unsigned long long k = s_buf[j];
                if (k > best) { best = k; bpos = j; }
            }
            #pragma unroll
            for (int o = 16; o > 0; o >>= 1) {
                unsigned long long ob = __shfl_down_sync(0xffffffffu, best, o);
                int op               = __shfl_down_sync(0xffffffffu, bpos, o);
                if (ob > best) { best = ob; bpos = op; }
            }
            if ((tid & 31) == 0) { s_wbest[tid >> 5] = best; s_wpos[tid >> 5] = bpos; }
            __syncthreads();
            if (tid == 0) {
                unsigned long long bb = 0ull; int bp = -1;
                #pragma unroll
                for (int w = 0; w < THREADS / 32; w++)
                    if (s_wbest[w] > bb) { bb = s_wbest[w]; bp = s_wpos[w]; }
                s_top[sel] = bb;
                if (bp >= 0) s_buf[bp] = 0ull;           // keys unique (idx) -> safe removal
            }
            __syncthreads();
        }
        if (tid < KVAL) s_buf[tid] = s_top[tid];
        if (tid == 0) {
            s_count = KVAL;
            s_thr   = (unsigned)(s_top[KVAL - 1] >> 32);
        }
        __syncthreads();
    };

    // ---------------- phase 0: first 2048 elements, fixed slots, one prune ----
    if (tid == 0) { s_count = 4 * THREADS; s_over = 0; }
    {
        float4 v = __ldcs(&r4[tid]);
        const int gi = 4 * tid;
        s_buf[gi + 0] = mk_key(v.x, gi + 0);
        s_buf[gi + 1] = mk_key(v.y, gi + 1);
        s_buf[gi + 2] = mk_key(v.z, gi + 2);
        s_buf[gi + 3] = mk_key(v.w, gi + 3);
    }
    __syncthreads();
    prune();                                   // row-wide threshold from 2048 samples
    const unsigned thr_u = s_thr;

    // ---------------- stream: barrier-free, 8 LDG.128 in flight per thread ----
    // remaining float4 indices: [512, 25000) -> 6 blocks of 8*512 (last predicated)
    #pragma unroll 1
    for (int blk = 0; blk < 6; blk++) {
        const int base = THREADS + blk * (UNR * THREADS) + tid;
        float4 v[UNR];
        int    ivec[UNR];
        bool   ok[UNR];
        #pragma unroll
        for (int u = 0; u < UNR; u++) {
            int i   = base + u * THREADS;
            ok[u]   = (i < NVEC);
            ivec[u] = ok[u] ? i : (NVEC - 1);  // clamped load keeps MLP, no divergence
            v[u]    = __ldcs(&r4[ivec[u]]);
        }
        #pragma unroll
        for (int u = 0; u < UNR; u++) {
            if (!ok[u]) continue;
            float4 q = v[u];
            float  m = fmaxf(fmaxf(q.x, q.y), fmaxf(q.z, q.w));
            if (flip_f32(m) >= thr_u) {        // ~0.5% of elements survive
                const int gi = ivec[u] * 4;
                #pragma unroll
                for (int e = 0; e < 4; e++) {
                    float qv = (e == 0) ? q.x : (e == 1) ? q.y : (e == 2) ? q.z : q.w;
                    if (flip_f32(qv) >= thr_u) {
                        int p = atomicAdd(&s_count, 1);
                        if (p < CAP) s_buf[p] = mk_key(qv, gi + e);
                        else         s_over  = 1;
                    }
                }
            }
        }
    }
    __syncthreads();
    const bool overflowed = (s_over != 0);
    __syncthreads();

    if (!overflowed) {
        // ~500 candidates (top-10-so-far in slots 0..9 + stream survivors)
        prune();
    } else {
        // -------- correctness fallback (adversarial inputs only): serial tiles
        if (tid == 0) { s_count = 0; s_thr = 0u; }
        __syncthreads();
        unsigned thr2 = 0u;                     // flip-domain; 0 passes everything
        #pragma unroll 1
        for (int basei = 0; basei < NVEC; basei += THREADS) {
            const int i = basei + tid;
            if (i < NVEC) {
                float4 q = __ldcs(&r4[i]);
                float  m = fmaxf(fmaxf(q.x, q.y), fmaxf(q.z, q.w));
                if (flip_f32(m) >= thr2) {
                    const int gi = i * 4;
                    #pragma unroll
                    for (int e = 0; e < 4; e++) {
                        float qv = (e == 0) ? q.x : (e == 1) ? q.y : (e == 2) ? q.z : q.w;
                        if (flip_f32(qv) >= thr2) {
                            int p = atomicAdd(&s_count, 1);
                            if (p < CAP) s_buf[p] = mk_key(qv, gi + e);
                        }
                    }
                }
            }
            __syncthreads();
            const int c = s_count;
            __syncthreads();
            if (c >= CAP - THREADS * 4) prune();  // guarantees room for next tile
            thr2 = s_thr;
        }
        __syncthreads();
        prune();
    }

    // ---- write out: [B*K indices (as float)] then [B*K scores]
    if (tid < KVAL) {
        unsigned long long key = s_top[tid];
        float val = unflip_f32((unsigned)(key >> 32));
        int   idx = (int)(~(unsigned)key);
        out[(size_t)row * KVAL + tid]                    = (float)idx;
        out[(size_t)B * KVAL + (size_t)row * KVAL + tid] = val;
    }
}

extern "C" void kernel_launch(void* const* d_in, const int* in_sizes, int n_in,
                              void* d_out, int out_size) {
    const float* scores = (const float*)d_in[0];
    const int B = in_sizes[0] / NCOLS;          // 2048
    (void)n_in; (void)out_size;
    topk_kernel<<<B, THREADS>>>(scores, (float*)d_out, B);
}

// round 7
// speedup vs baseline: 8.6488x; 1.0385x over previous
#include <cuda_runtime.h>
#include <cstdint>

#define THREADS 512
#define NWARP   (THREADS / 32)
#define KVAL    10
#define NCOLS   100000
#define NVEC    (NCOLS / 4)       // 25000 float4 per row
#define CAP     4096              // candidate buffer (uint64 keys)
#define UNR     8                 // loads in flight per thread (stream)
#define SAMPV   THREADS           // sample = first 512 float4s (2048 elems)
#define MAXL    (CAP / THREADS)   // 8 merge keys per thread max

// Monotonic bijection fp32 -> uint32 (order-preserving, no NaNs in data).
__device__ __forceinline__ unsigned flip_f32(float f) {
    unsigned u = __float_as_uint(f);
    return (u & 0x80000000u) ? ~u : (u | 0x80000000u);
}
__device__ __forceinline__ float unflip_f32(unsigned u) {
    unsigned b = (u & 0x80000000u) ? (u ^ 0x80000000u) : ~u;
    return __uint_as_float(b);
}
// key = (flip(v)<<32) | ~idx : u64 max == larger value, then smaller index.
// Low 32 bits = ~idx != 0 always (idx < 2^17), so 0 is a safe empty sentinel.
__device__ __forceinline__ unsigned long long mk_key(float v, int idx) {
    return ((unsigned long long)flip_f32(v) << 32) | (unsigned)(~idx);
}

// Warp-collective (warp 0): over 256-bin hist, find largest bin b with
// suffix-count(>=b) >= K. Returns b; *above = count strictly above bin b.
__device__ __forceinline__ int hist_find(const int* hist, int K, int lane,
                                         int* above) {
    int h[8]; int s = 0;
    #pragma unroll
    for (int t = 0; t < 8; t++) { h[t] = hist[lane * 8 + t]; s += h[t]; }
    int cum = s;                               // suffix-inclusive across lanes
    #pragma unroll
    for (int o = 1; o < 32; o <<= 1) {
        int t = __shfl_down_sync(0xffffffffu, cum, o);
        if (lane + o < 32) cum += t;
    }
    unsigned bal = __ballot_sync(0xffffffffu, cum >= K);
    int lstar = 31 - __clz(bal);               // cum(lane0)=total>=K guaranteed
    int nxt = (lstar < 31) ? lstar + 1 : 0;
    int above_lane = __shfl_sync(0xffffffffu, cum, nxt);
    if (lstar == 31) above_lane = 0;
    int bin = -1, abv = 0, acc = above_lane;
    if (lane == lstar) {
        #pragma unroll
        for (int t = 7; t >= 0; t--) {
            bool hit = (bin < 0) && (acc + h[t] >= K);
            if (hit) { bin = lane * 8 + t; abv = acc; }
            acc += h[t];
        }
    }
    bin  = __shfl_sync(0xffffffffu, bin, lstar);
    *above = __shfl_sync(0xffffffffu, abv, lstar);
    return bin;
}

__global__ __launch_bounds__(THREADS, 2)
void topk_kernel(const float* __restrict__ scores, float* __restrict__ out, int B) {
    __shared__ unsigned long long s_buf[CAP];               // 32 KB
    __shared__ unsigned long long s_warp10[NWARP * KVAL];   // 160 keys
    __shared__ unsigned long long s_top[KVAL];
    __shared__ unsigned long long s_wbest[NWARP];
    __shared__ int                s_wpos[NWARP];
    __shared__ int                s_hist1[256];
    __shared__ int                s_hist2[256];
    __shared__ int                s_count;
    __shared__ int                s_over;
    __shared__ unsigned           s_thr;
    __shared__ int                s_b1, s_r;

    const int tid  = threadIdx.x;
    const int lane = tid & 31;
    const int wid  = tid >> 5;
    const int row  = blockIdx.x;
    const float4* __restrict__ r4 = (const float4*)(scores + (size_t)row * NCOLS);

    // ---- exact selection-with-removal (FALLBACK PATH ONLY) ----
    auto prune = [&]() {
        const int c = min(s_count, CAP);
        #pragma unroll 1
        for (int sel = 0; sel < KVAL; sel++) {
            unsigned long long best = 0ull; int bpos = -1;
            for (int j = tid; j < c; j += THREADS) {
                unsigned long long k = s_buf[j];
                if (k > best) { best = k; bpos = j; }
            }
            #pragma unroll
            for (int o = 16; o > 0; o >>= 1) {
                unsigned long long ob = __shfl_down_sync(0xffffffffu, best, o);
                int op               = __shfl_down_sync(0xffffffffu, bpos, o);
                if (ob > best) { best = ob; bpos = op; }
            }
            if (lane == 0) { s_wbest[wid] = best; s_wpos[wid] = bpos; }
            __syncthreads();
            if (tid == 0) {
                unsigned long long bb = 0ull; int bp = -1;
                #pragma unroll
                for (int w = 0; w < NWARP; w++)
                    if (s_wbest[w] > bb) { bb = s_wbest[w]; bp = s_wpos[w]; }
                s_top[sel] = bb;
                if (bp >= 0) s_buf[bp] = 0ull;
            }
            __syncthreads();
        }
        if (tid < KVAL) s_buf[tid] = s_top[tid];
        if (tid == 0) { s_count = KVAL; s_thr = (unsigned)(s_top[KVAL - 1] >> 32); }
        __syncthreads();
    };

    // ================= phase 0: histogram threshold from 2048-elem sample ====
    if (tid < 256) { s_hist1[tid] = 0; s_hist2[tid] = 0; }
    if (tid == 0)  { s_count = 0; s_over = 0; }
    __syncthreads();

    const float4 v0 = __ldcs(&r4[tid]);              // sample float4, kept in regs
    unsigned f0[4] = { flip_f32(v0.x), flip_f32(v0.y), flip_f32(v0.z), flip_f32(v0.w) };
    #pragma unroll
    for (int e = 0; e < 4; e++) atomicAdd(&s_hist1[f0[e] >> 24], 1);
    __syncthreads();

    if (wid == 0) {
        int above1;
        int b1 = hist_find(s_hist1, KVAL, lane, &above1);
        if (lane == 0) { s_b1 = b1; s_r = KVAL - above1; }   // 1..10 needed in bin b1
    }
    __syncthreads();

    const int b1 = s_b1;
    #pragma unroll
    for (int e = 0; e < 4; e++)
        if ((int)(f0[e] >> 24) == b1) atomicAdd(&s_hist2[(f0[e] >> 16) & 0xFF], 1);
    __syncthreads();

    if (wid == 0) {
        int above2;
        int b2 = hist_find(s_hist2, s_r, lane, &above2);
        if (lane == 0) s_thr = ((unsigned)b1 << 24) | ((unsigned)b2 << 16);
    }
    __syncthreads();

    const unsigned thr_u = s_thr;
    const float    thr_f = unflip_f32(thr_u);

    // append sample survivors (>=10 guaranteed by construction)
    #pragma unroll
    for (int e = 0; e < 4; e++) {
        if (f0[e] >= thr_u) {
            int p = atomicAdd(&s_count, 1);
            if (p < CAP) s_buf[p] = ((unsigned long long)f0[e] << 32)
                                  | (unsigned)(~(4 * tid + e));
            else         s_over = 1;
        }
    }

    // ================= stream: barrier-free, 8 LDG.128 in flight =============
    // indices [512, 25000): 5 full UNR blocks (20480) + 1 predicated tail (4008)
    #pragma unroll 1
    for (int blk = 0; blk < 5; blk++) {
        const int base = SAMPV + blk * (UNR * THREADS) + tid;
        float4 v[UNR];
        #pragma unroll
        for (int u = 0; u < UNR; u++) v[u] = __ldcs(&r4[base + u * THREADS]);
        #pragma unroll
        for (int u = 0; u < UNR; u++) {
            float4 q = v[u];
            float  m = fmaxf(fmaxf(q.x, q.y), fmaxf(q.z, q.w));
            if (m >= thr_f) {                      // ~0.5% of vectors
                const int gi = (base + u * THREADS) * 4;
                float qv[4] = {q.x, q.y, q.z, q.w};
                #pragma unroll
                for (int e = 0; e < 4; e++) {
                    if (qv[e] >= thr_f) {
                        int p = atomicAdd(&s_count, 1);
                        if (p < CAP) s_buf[p] = mk_key(qv[e], gi + e);
                        else         s_over  = 1;
                    }
                }
            }
        }
    }
    {   // tail block, predicated
        const int base = SAMPV + 5 * (UNR * THREADS) + tid;   // 20992 + tid
        float4 v[UNR]; int iv[UNR]; bool ok[UNR];
        #pragma unroll
        for (int u = 0; u < UNR; u++) {
            int i = base + u * THREADS;
            ok[u] = (i < NVEC);
            iv[u] = ok[u] ? i : (NVEC - 1);
            v[u]  = __ldcs(&r4[iv[u]]);
        }
        #pragma unroll
        for (int u = 0; u < UNR; u++) {
            if (!ok[u]) continue;
            float4 q = v[u];
            float  m = fmaxf(fmaxf(q.x, q.y), fmaxf(q.z, q.w));
            if (m >= thr_f) {
                const int gi = iv[u] * 4;
                float qv[4] = {q.x, q.y, q.z, q.w};
                #pragma unroll
                for (int e = 0; e < 4; e++) {
                    if (qv[e] >= thr_f) {
                        int p = atomicAdd(&s_count, 1);
                        if (p < CAP) s_buf[p] = mk_key(qv[e], gi + e);
                        else         s_over  = 1;
                    }
                }
            }
        }
    }
    __syncthreads();

    const int  c          = min(s_count, CAP);
    const bool overflowed = (s_over != 0);

    if (!overflowed) {
        // ============== final: 2-stage register tournament over ~500 keys ====
        unsigned long long L[MAXL];
        #pragma unroll
        for (int s = 0; s < MAXL; s++) {
            int j = tid + s * THREADS;
            L[s] = (j < c) ? s_buf[j] : 0ull;
        }
        #pragma unroll 1
        for (int round = 0; round < KVAL; round++) {       // warp-local top-10
            unsigned long long best = 0ull; int bslot = 0;
            #pragma unroll
            for (int s = 0; s < MAXL; s++)
                if (L[s] > best) { best = L[s]; bslot = s; }
            unsigned long long b = best; int who = lane;
            #pragma unroll
            for (int o = 16; o > 0; o >>= 1) {
                unsigned long long ob = __shfl_down_sync(0xffffffffu, b, o);
                int ow               = __shfl_down_sync(0xffffffffu, who, o);
                if (ob > b) { b = ob; who = ow; }
            }
            b   = __shfl_sync(0xffffffffu, b, 0);
            who = __shfl_sync(0xffffffffu, who, 0);
            if (lane == who) L[bslot] = 0ull;              // remove winner
            if (lane == 0) s_warp10[wid * KVAL + round] = b;
        }
        __syncthreads();
        if (wid == 0) {                                    // 160 -> top-10
            unsigned long long M[5];
            #pragma unroll
            for (int t = 0; t < 5; t++) M[t] = s_warp10[lane * 5 + t];
            #pragma unroll 1
            for (int round = 0; round < KVAL; round++) {
                unsigned long long best = 0ull; int bslot = 0;
                #pragma unroll
                for (int t = 0; t < 5; t++)
                    if (M[t] > best) { best = M[t]; bslot = t; }
                unsigned long long b = best; int who = lane;
                #pragma unroll
                for (int o = 16; o > 0; o >>= 1) {
                    unsigned long long ob = __shfl_down_sync(0xffffffffu, b, o);
                    int ow               = __shfl_down_sync(0xffffffffu, who, o);
                    if (ob > b) { b = ob; who = ow; }
                }
                b   = __shfl_sync(0xffffffffu, b, 0);
                who = __shfl_sync(0xffffffffu, who, 0);
                if (lane == who) M[bslot] = 0ull;
                if (lane == 0) s_top[round] = b;
            }
        }
        __syncthreads();
    } else {
        // ============== correctness fallback: serial tiles + exact prunes ====
        if (tid == 0) { s_count = 0; s_thr = 0u; }
        __syncthreads();
        unsigned thr2 = 0u;
        #pragma unroll 1
        for (int basei = 0; basei < NVEC; basei += THREADS) {
            const int i = basei + tid;
            if (i < NVEC) {
                float4 q = __ldcs(&r4[i]);
                float  m = fmaxf(fmaxf(q.x, q.y), fmaxf(q.z, q.w));
                if (flip_f32(m) >= thr2) {
                    const int gi = i * 4;
                    float qv[4] = {q.x, q.y, q.z, q.w};
                    #pragma unroll
                    for (int e = 0; e < 4; e++) {
                        if (flip_f32(qv[e]) >= thr2) {
                            int p = atomicAdd(&s_count, 1);
                            if (p < CAP) s_buf[p] = mk_key(qv[e], gi + e);
                        }
                    }
                }
            }
            __syncthreads();
            const int cc = s_count;
            __syncthreads();
            if (cc >= CAP - THREADS * 4) prune();
            thr2 = s_thr;
        }
        __syncthreads();
        prune();
    }

    // ---- write out: [B*K indices (as float)] then [B*K scores]
    if (tid < KVAL) {
        unsigned long long key = s_top[tid];
        float val = unflip_f32((unsigned)(key >> 32));
        int   idx = (int)(~(unsigned)key);
        out[(size_t)row * KVAL + tid]                    = (float)idx;
        out[(size_t)B * KVAL + (size_t)row * KVAL + tid] = val;
    }
}

extern "C" void kernel_launch(void* const* d_in, const int* in_sizes, int n_in,
                              void* d_out, int out_size) {
    const float* scores = (const float*)d_in[0];
    const int B = in_sizes[0] / NCOLS;          // 2048
    (void)n_in; (void)out_size;
    topk_kernel<<<B, THREADS>>>(scores, (float*)d_out, B);
}

// round 10
// speedup vs baseline: 8.7266x; 1.0090x over previous
#include <cuda_runtime.h>
#include <cstdint>

#define THREADS 512
#define NWARP   (THREADS / 32)
#define KVAL    10
#define NCOLS   100000
#define NVEC    (NCOLS / 4)       // 25000 float4 per row
#define CAP     4096              // candidate buffer (uint64 keys)
#define UNR     8                 // loads in flight per thread (stream)
#define SAMPV   THREADS           // sample = first 512 float4s (2048 elems)
#define MAXL    (CAP / THREADS)   // 8 merge keys per thread max

// Monotonic bijection fp32 -> uint32 (order-preserving, no NaNs in data).
__device__ __forceinline__ unsigned flip_f32(float f) {
    unsigned u = __float_as_uint(f);
    return (u & 0x80000000u) ? ~u : (u | 0x80000000u);
}
__device__ __forceinline__ unsigned flip_bits(unsigned u) {
    return (u & 0x80000000u) ? ~u : (u | 0x80000000u);
}
__device__ __forceinline__ float unflip_f32(unsigned u) {
    unsigned b = (u & 0x80000000u) ? (u ^ 0x80000000u) : ~u;
    return __uint_as_float(b);
}
// key = (flip(v)<<32) | ~idx : u64 max == larger value, then smaller index.
__device__ __forceinline__ unsigned long long mk_key(float v, int idx) {
    return ((unsigned long long)flip_f32(v) << 32) | (unsigned)(~idx);
}
__device__ __forceinline__ unsigned long long mk_key_bits(int bits, int idx) {
    return ((unsigned long long)flip_bits((unsigned)bits) << 32) | (unsigned)(~idx);
}

// 3-way signed max (DPX on sm_90+: single VIMNMX3)
__device__ __forceinline__ int max3(int a, int b, int c) {
#if __CUDA_ARCH__ >= 900
    return __vimax3_s32(a, b, c);
#else
    return max(max(a, b), c);
#endif
}

// Warp-collective (warp 0): over 256-bin hist, find largest bin b with
// suffix-count(>=b) >= K. Returns b; *above = count strictly above bin b.
__device__ __forceinline__ int hist_find(const int* hist, int K, int lane,
                                         int* above) {
    int h[8]; int s = 0;
    #pragma unroll
    for (int t = 0; t < 8; t++) { h[t] = hist[lane * 8 + t]; s += h[t]; }
    int cum = s;                               // suffix-inclusive across lanes
    #pragma unroll
    for (int o = 1; o < 32; o <<= 1) {
        int t = __shfl_down_sync(0xffffffffu, cum, o);
        if (lane + o < 32) cum += t;
    }
    unsigned bal = __ballot_sync(0xffffffffu, cum >= K);
    int lstar = 31 - __clz(bal);
    int nxt = (lstar < 31) ? lstar + 1 : 0;
    int above_lane = __shfl_sync(0xffffffffu, cum, nxt);
    if (lstar == 31) above_lane = 0;
    int bin = -1, abv = 0, acc = above_lane;
    if (lane == lstar) {
        #pragma unroll
        for (int t = 7; t >= 0; t--) {
            bool hit = (bin < 0) && (acc + h[t] >= K);
            if (hit) { bin = lane * 8 + t; abv = acc; }
            acc += h[t];
        }
    }
    bin  = __shfl_sync(0xffffffffu, bin, lstar);
    *above = __shfl_sync(0xffffffffu, abv, lstar);
    return bin;
}

__global__ __launch_bounds__(THREADS, 2)
void topk_kernel(const float* __restrict__ scores, float* __restrict__ out, int B) {
    __shared__ unsigned long long s_buf[CAP];               // 32 KB
    __shared__ unsigned long long s_warp10[NWARP * KVAL];
    __shared__ unsigned long long s_top[KVAL];
    __shared__ unsigned long long s_wbest[NWARP];
    __shared__ int                s_wpos[NWARP];
    __shared__ int                s_hist1[256];
    __shared__ int                s_hist2[256];
    __shared__ int                s_count;
    __shared__ int                s_over;
    __shared__ unsigned           s_thr;
    __shared__ int                s_b1, s_r;

    const int tid  = threadIdx.x;
    const int lane = tid & 31;
    const int wid  = tid >> 5;
    const int row  = blockIdx.x;
    const float* __restrict__ rp = scores + (size_t)row * NCOLS;
    const float4* __restrict__ r4 = (const float4*)rp;
    const int4*   __restrict__ r4i = (const int4*)rp;

    // ---- exact selection-with-removal (FALLBACK PATH ONLY) ----
    auto prune = [&]() {
        const int c = min(s_count, CAP);
        #pragma unroll 1
        for (int sel = 0; sel < KVAL; sel++) {
            unsigned long long best = 0ull; int bpos = -1;
            for (int j = tid; j < c; j += THREADS) {
                unsigned long long k = s_buf[j];
                if (k > best) { best = k; bpos = j; }
            }
            #pragma unroll
            for (int o = 16; o > 0; o >>= 1) {
                unsigned long long ob = __shfl_down_sync(0xffffffffu, best, o);
                int op               = __shfl_down_sync(0xffffffffu, bpos, o);
                if (ob > best) { best = ob; bpos = op; }
            }
            if (lane == 0) { s_wbest[wid] = best; s_wpos[wid] = bpos; }
            __syncthreads();
            if (tid == 0) {
                unsigned long long bb = 0ull; int bp = -1;
                #pragma unroll
                for (int w = 0; w < NWARP; w++)
                    if (s_wbest[w] > bb) { bb = s_wbest[w]; bp = s_wpos[w]; }
                s_top[sel] = bb;
                if (bp >= 0) s_buf[bp] = 0ull;
            }
            __syncthreads();
        }
        if (tid < KVAL) s_buf[tid] = s_top[tid];
        if (tid == 0) { s_count = KVAL; s_thr = (unsigned)(s_top[KVAL - 1] >> 32); }
        __syncthreads();
    };

    // ================= phase 0: histogram threshold from 2048-elem sample ====
    if (tid < 256) { s_hist1[tid] = 0; s_hist2[tid] = 0; }
    if (tid == 0)  { s_count = 0; s_over = 0; }
    __syncthreads();

    const float4 v0 = __ldcs(&r4[tid]);
    unsigned f0[4] = { flip_f32(v0.x), flip_f32(v0.y), flip_f32(v0.z), flip_f32(v0.w) };
    #pragma unroll
    for (int e = 0; e < 4; e++) atomicAdd(&s_hist1[f0[e] >> 24], 1);
    __syncthreads();

    if (wid == 0) {
        int above1;
        int b1 = hist_find(s_hist1, KVAL, lane, &above1);
        if (lane == 0) { s_b1 = b1; s_r = KVAL - above1; }
    }
    __syncthreads();

    const int b1 = s_b1;
    #pragma unroll
    for (int e = 0; e < 4; e++)
        if ((int)(f0[e] >> 24) == b1) atomicAdd(&s_hist2[(f0[e] >> 16) & 0xFF], 1);
    __syncthreads();

    if (wid == 0) {
        int above2;
        int b2 = hist_find(s_hist2, s_r, lane, &above2);
        if (lane == 0) s_thr = ((unsigned)b1 << 24) | ((unsigned)b2 << 16);
    }
    __syncthreads();

    const unsigned thr_u = s_thr;
    const float    thr_f = unflip_f32(thr_u);
    const int      thr_i = __float_as_int(thr_f);
    // int-domain compare trick requires positive threshold
    const bool     int_ok = (thr_f > 0.0f);
    if (!int_ok && tid == 0) s_over = 1;     // route to exact fallback

    // append sample survivors (>=10 guaranteed by construction)
    #pragma unroll
    for (int e = 0; e < 4; e++) {
        if (f0[e] >= thr_u) {
            int p = atomicAdd(&s_count, 1);
            if (p < CAP) s_buf[p] = ((unsigned long long)f0[e] << 32)
                                  | (unsigned)(~(4 * tid + e));
            else         s_over = 1;
        }
    }

    // push for stream survivors (int-bits domain)
    auto pushv = [&](int4 q, int gi) {
        if (q.x >= thr_i) { int p = atomicAdd(&s_count, 1);
            if (p < CAP) s_buf[p] = mk_key_bits(q.x, gi + 0); else s_over = 1; }
        if (q.y >= thr_i) { int p = atomicAdd(&s_count, 1);
            if (p < CAP) s_buf[p] = mk_key_bits(q.y, gi + 1); else s_over = 1; }
        if (q.z >= thr_i) { int p = atomicAdd(&s_count, 1);
            if (p < CAP) s_buf[p] = mk_key_bits(q.z, gi + 2); else s_over = 1; }
        if (q.w >= thr_i) { int p = atomicAdd(&s_count, 1);
            if (p < CAP) s_buf[p] = mk_key_bits(q.w, gi + 3); else s_over = 1; }
    };
    // 16-element max via vimax3 tree (8 ops)
    auto max16 = [&](int4 a, int4 b, int4 c, int4 d) {
        int t0 = max3(a.x, a.y, a.z);
        int t1 = max3(a.w, b.x, b.y);
        int t2 = max3(b.z, b.w, c.x);
        int t3 = max3(c.y, c.z, c.w);
        int t4 = max3(d.x, d.y, d.z);
        int u0 = max3(t0, t1, t2);
        int u1 = max3(t3, t4, d.w);
        return max(u0, u1);
    };

    // ================= stream: 8 LDG.128 in flight, 1 branch / 4 vectors ====
    if (int_ok) {
        #pragma unroll 1
        for (int blk = 0; blk < 5; blk++) {
            const int base = SAMPV + blk * (UNR * THREADS) + tid;
            int4 v[UNR];
            #pragma unroll
            for (int u = 0; u < UNR; u++) v[u] = __ldcs(&r4i[base + u * THREADS]);
            // group A: v[0..3]
            if (max16(v[0], v[1], v[2], v[3]) >= thr_i) {
                #pragma unroll
                for (int u = 0; u < 4; u++) pushv(v[u], (base + u * THREADS) * 4);
            }
            // group B: v[4..7]
            if (max16(v[4], v[5], v[6], v[7]) >= thr_i) {
                #pragma unroll
                for (int u = 4; u < 8; u++) pushv(v[u], (base + u * THREADS) * 4);
            }
        }
        {   // tail block, per-vector predicated
            const int base = SAMPV + 5 * (UNR * THREADS) + tid;   // 20992 + tid
            int4 v[UNR]; int iv[UNR]; bool ok[UNR];
            #pragma unroll
            for (int u = 0; u < UNR; u++) {
                int i = base + u * THREADS;
                ok[u] = (i < NVEC);
                iv[u] = ok[u] ? i : (NVEC - 1);
                v[u]  = __ldcs(&r4i[iv[u]]);
            }
            #pragma unroll
            for (int u = 0; u < UNR; u++) {
                if (!ok[u]) continue;
                int m = max3(max3(v[u].x, v[u].y, v[u].z), v[u].w, thr_i - 1);
                if (m >= thr_i) pushv(v[u], iv[u] * 4);
            }
        }
    }
    __syncthreads();

    const int  c          = min(s_count, CAP);
    const bool overflowed = (s_over != 0);

    if (!overflowed) {
        // ============== final: 2-stage register tournament over ~500 keys ====
        unsigned long long L[MAXL];
        #pragma unroll
        for (int s = 0; s < MAXL; s++) {
            int j = tid + s * THREADS;
            L[s] = (j < c) ? s_buf[j] : 0ull;
        }
        #pragma unroll 1
        for (int round = 0; round < KVAL; round++) {       // warp-local top-10
            unsigned long long best = 0ull; int bslot = 0;
            #pragma unroll
            for (int s = 0; s < MAXL; s++)
                if (L[s] > best) { best = L[s]; bslot = s; }
            unsigned long long b = best; int who = lane;
            #pragma unroll
            for (int o = 16; o > 0; o >>= 1) {
                unsigned long long ob = __shfl_down_sync(0xffffffffu, b, o);
                int ow               = __shfl_down_sync(0xffffffffu, who, o);
                if (ob > b) { b = ob; who = ow; }
            }
            b   = __shfl_sync(0xffffffffu, b, 0);
            who = __shfl_sync(0xffffffffu, who, 0);
            if (lane == who) L[bslot] = 0ull;
            if (lane == 0) s_warp10[wid * KVAL + round] = b;
        }
        __syncthreads();
        if (wid == 0) {                                    // 160 -> top-10
            unsigned long long M[5];
            #pragma unroll
            for (int t = 0; t < 5; t++) M[t] = s_warp10[lane * 5 + t];
            #pragma unroll 1
            for (int round = 0; round < KVAL; round++) {
                unsigned long long best = 0ull; int bslot = 0;
                #pragma unroll
                for (int t = 0; t < 5; t++)
                    if (M[t] > best) { best = M[t]; bslot = t; }
                unsigned long long b = best; int who = lane;
                #pragma unroll
                for (int o = 16; o > 0; o >>= 1) {
                    unsigned long long ob = __shfl_down_sync(0xffffffffu, b, o);
                    int ow               = __shfl_down_sync(0xffffffffu, who, o);
                    if (ob > b) { b = ob; who = ow; }
                }
                b   = __shfl_sync(0xffffffffu, b, 0);
                who = __shfl_sync(0xffffffffu, who, 0);
                if (lane == who) M[bslot] = 0ull;
                if (lane == 0) s_top[round] = b;
            }
        }
        __syncthreads();
    } else {
        // ============== correctness fallback: serial tiles + exact prunes ====
        if (tid == 0) { s_count = 0; s_thr = 0u; }
        __syncthreads();
        unsigned thr2 = 0u;
        #pragma unroll 1
        for (int basei = 0; basei < NVEC; basei += THREADS) {
            const int i = basei + tid;
            if (i < NVEC) {
                float4 q = __ldcs(&r4[i]);
                float  m = fmaxf(fmaxf(q.x, q.y), fmaxf(q.z, q.w));
                if (flip_f32(m) >= thr2) {
                    const int gi = i * 4;
                    float qv[4] = {q.x, q.y, q.z, q.w};
                    #pragma unroll
                    for (int e = 0; e < 4; e++) {
                        if (flip_f32(qv[e]) >= thr2) {
                            int p = atomicAdd(&s_count, 1);
                            if (p < CAP) s_buf[p] = mk_key(qv[e], gi + e);
                        }
                    }
                }
            }
            __syncthreads();
            const int cc = s_count;
            __syncthreads();
            if (cc >= CAP - THREADS * 4) prune();
            thr2 = s_thr;
        }
        __syncthreads();
        prune();
    }

    // ---- write out: [B*K indices (as float)] then [B*K scores]
    if (tid < KVAL) {
        unsigned long long key = s_top[tid];
        float val = unflip_f32((unsigned)(key >> 32));
        int   idx = (int)(~(unsigned)key);
        out[(size_t)row * KVAL + tid]                    = (float)idx;
        out[(size_t)B * KVAL + (size_t)row * KVAL + tid] = val;
    }
}

extern "C" void kernel_launch(void* const* d_in, const int* in_sizes, int n_in,
                              void* d_out, int out_size) {
    const float* scores = (const float*)d_in[0];
    const int B = in_sizes[0] / NCOLS;          // 2048
    (void)n_in; (void)out_size;
    topk_kernel<<<B, THREADS>>>(scores, (float*)d_out, B);
}